// round 11
// baseline (speedup 1.0000x reference)
#include <cuda_runtime.h>
#include <cstdint>

// Problem sizes
#define S    4096
#define II   64
#define H    1024
#define NCTA 128
#define UPC  8        // hidden units per CTA (1 per warp, 8 warps)

// ---------------------------------------------------------------------------
// Device-global scratch (allocation-free rule: __device__ arrays only)
//
// g_hq: double-buffered hidden state, one 8-byte atom per unit:
//       low 32 = h (f32 bits), high 32 = step tag. h_t lives in slot t&1,
//       tag == t. Publish/poll via st/ld.relaxed.gpu.b64 (morally strong
//       <=64b => single-copy atomic; proven correct in R7).
//
// NO counter, NO flags, NO turnstile: signal and data are the same atom,
// so the whole exchange is ONE L2 round trip. R7's failure was not
// correctness but poll FLOOD (437 req/cy > ~184 LTS cap); fixed here by
// two-phase polling: tight spin on ONE atom per thread (dependent-load
// loop = 1 req/RT/thread ~= 110 req/cy chip-wide), then a single burst
// for the remaining 3 atoms (same 32B sector) with rare retries.
// ---------------------------------------------------------------------------
__device__ unsigned long long g_hq[2][H];

// ---------------------------------------------------------------------------
// Helpers
// ---------------------------------------------------------------------------
__device__ __forceinline__ unsigned long long pk2(float x, float y) {
    unsigned long long r;
    asm("mov.b64 %0, {%1,%2};" : "=l"(r) : "f"(x), "f"(y));
    return r;
}
__device__ __forceinline__ void upk2(unsigned long long a, float& x, float& y) {
    asm("mov.b64 {%0,%1}, %2;" : "=f"(x), "=f"(y) : "l"(a));
}
__device__ __forceinline__ unsigned long long pk_fu(float x, unsigned t) {
    unsigned long long r;
    asm("mov.b64 %0, {%1,%2};" : "=l"(r) : "f"(x), "r"(t));
    return r;
}
#define FMA2(acc, a, b) \
    asm("fma.rn.f32x2 %0, %1, %2, %0;" : "+l"(acc) : "l"(a), "l"(b))

__device__ __forceinline__ float sigf(float x) {
    return 1.0f / (1.0f + __expf(-x));
}
__device__ __forceinline__ float tanhfast(float x) {
    float ax = fabsf(x);
    float e  = __expf(-2.0f * ax);          // in (0,1], overflow-free
    float t  = __fdividef(1.0f - e, 1.0f + e);
    return copysignf(t, x);
}

// ---------------------------------------------------------------------------
// Kernel 0: reset state between graph replays (determinism requirement)
// slot 0: tag 0 / h = 0  ->  step-0 poll passes immediately with h_0 = 0.
// ---------------------------------------------------------------------------
__global__ void reset_kernel() {
    int i = threadIdx.x;
    if (i < H) { g_hq[0][i] = 0ull; g_hq[1][i] = 0ull; }
}

// ---------------------------------------------------------------------------
// Kernel 1: persistent fused LSTM recurrence (input GEMM folded in).
// 128 CTAs x 256 threads, 1 CTA/SM. Warp w of CTA b owns hidden unit
// u = b*8 + w (gate rows u, H+u, 2H+u, 3H+u). Lane l holds W_hh column
// pairs (2l+64k) k=0..15 (64 packed f32x2) + W_ih column pair 2l in regs.
//
// Per-step protocol (ONE __syncthreads, zero fences, zero atRED):
//   1. prefetch x_{t+1} (tid<16, 256 B, triple-buffered SMEM)
//   2. POLL phase 1: spin ld.relaxed.b64 on atom 4*tid until tag == t
//      (thread's 4 atoms = units 4tid..4tid+3, all from ONE producer CTA,
//       so atom 0 fresh => 1..3 almost surely fresh too)
//      POLL phase 2: burst-load atoms +1,+2,+3 (same 32B sector); retry any
//      stale (rare)
//   3. stage 4 h values -> hs[t&1] (STS.128), __syncthreads
//   4. matvec (LDS.64 + FMA2, W_hh + W_ih) -> shfl reduce -> activations
//   5. lane 0: st.relaxed.gpu.b64 {h_new, t+1} into slot (t+1)&1 — that
//      single atomic store is both data AND signal. Nothing else.
//
// Ordering safety (R7 argument, verbatim): a warp enters step t+1 only
// after observing tag t+1 on all its atoms, which exists only after every
// warp chip-wide (incl. its own CTA) finished step t. Hence intra-CTA skew
// < 1 step (hs double-buffer + xs triple-buffer suffice, one bar aligns
// stage-writes vs matvec-reads), and slot (t+1)&1 is rewritten only after
// every reader of its previous occupancy (step t-1 readers) completed.
// ---------------------------------------------------------------------------
__global__ void __launch_bounds__(256, 1) rec_kernel(
    const float* __restrict__ x,
    const float* __restrict__ Wih,
    const float* __restrict__ Whh,
    const float* __restrict__ bih,
    const float* __restrict__ bhh)
{
    __shared__ __align__(16) float hs[2][H];     // staged h_t
    __shared__ __align__(16) float xs[3][II];    // staged x_t (triple buffer)

    const int tid  = threadIdx.x;
    const int lane = tid & 31;
    const int wrp  = tid >> 5;               // 0..7
    const int u    = blockIdx.x * UPC + wrp; // hidden unit 0..1023

    // ---- W_hh slice into registers (coalesced float2 loads) ----
    unsigned long long wq[4][16];
    #pragma unroll
    for (int g = 0; g < 4; g++) {
        const float2* base = (const float2*)(Whh + (size_t)(g * H + u) * H) + lane;
        #pragma unroll
        for (int k = 0; k < 16; k++) {
            float2 v = base[k * 32];
            wq[g][k] = pk2(v.x, v.y);
        }
    }
    // ---- W_ih slice (cols 2l, 2l+1 of rows u, H+u, 2H+u, 3H+u) ----
    unsigned long long wx[4];
    #pragma unroll
    for (int g = 0; g < 4; g++) {
        float2 v = ((const float2*)(Wih + (size_t)(g * H + u) * II))[lane];
        wx[g] = pk2(v.x, v.y);
    }
    // ---- biases (only lane 0 consumes them) ----
    float bs0 = bih[u]         + bhh[u];
    float bs1 = bih[H + u]     + bhh[H + u];
    float bs2 = bih[2 * H + u] + bhh[2 * H + u];
    float bs3 = bih[3 * H + u] + bhh[3 * H + u];

    // ---- preload x_0 into xs[0] ----
    if (tid < 16) ((float4*)xs[0])[tid] = ((const float4*)x)[tid];
    __syncthreads();

    float c = 0.0f;                          // cell state (lane 0 only)
    const unsigned full = 0xffffffffu;

    const unsigned long long* mypoll = &g_hq[0][0] + 4 * tid;  // + slot*H per step

    #pragma unroll 1
    for (int t = 0; t < S; t++) {
        const int cur = t & 1;

        // 1. prefetch next step's input row (DRAM, hidden behind this step)
        if (t + 1 < S && tid < 16)
            ((float4*)xs[(t + 1) % 3])[tid] =
                __ldcg((const float4*)(x + (size_t)(t + 1) * II) + tid);

        // 2a. phase 1: rate-limited spin on atom 0 (dependent-load loop)
        const unsigned long long* p = mypoll + (size_t)cur * H;
        unsigned long long q0, q1, q2, q3;
        do {
            asm volatile("ld.relaxed.gpu.global.b64 %0, [%1];" : "=l"(q0) : "l"(p));
        } while ((unsigned)(q0 >> 32) != (unsigned)t);

        // 2b. phase 2: burst the sibling atoms (same 32B sector), rare retry
        do {
            asm volatile("ld.relaxed.gpu.global.b64 %0, [%1];" : "=l"(q1) : "l"(p + 1));
            asm volatile("ld.relaxed.gpu.global.b64 %0, [%1];" : "=l"(q2) : "l"(p + 2));
            asm volatile("ld.relaxed.gpu.global.b64 %0, [%1];" : "=l"(q3) : "l"(p + 3));
        } while ((unsigned)(q1 >> 32) != (unsigned)t ||
                 (unsigned)(q2 >> 32) != (unsigned)t ||
                 (unsigned)(q3 >> 32) != (unsigned)t);

        // 3. stage into SMEM (single STS.128 per thread)
        float4 hv4;
        hv4.x = __uint_as_float((unsigned)q0);
        hv4.y = __uint_as_float((unsigned)q1);
        hv4.z = __uint_as_float((unsigned)q2);
        hv4.w = __uint_as_float((unsigned)q3);
        ((float4*)hs[cur])[tid] = hv4;
        __syncthreads();                     // the ONE bar per step

        // 4. mat-vec: W_hh * h_t  +  W_ih * x_t  (all packed f32x2)
        unsigned long long a0 = 0ull, a1 = 0ull, a2 = 0ull, a3 = 0ull;
        const unsigned long long* h2p = (const unsigned long long*)hs[cur] + lane;
        #pragma unroll
        for (int k = 0; k < 16; k++) {
            unsigned long long hv = h2p[k * 32];
            FMA2(a0, wq[0][k], hv);
            FMA2(a1, wq[1][k], hv);
            FMA2(a2, wq[2][k], hv);
            FMA2(a3, wq[3][k], hv);
        }
        {
            unsigned long long xv = ((const unsigned long long*)xs[t % 3])[lane];
            FMA2(a0, wx[0], xv);
            FMA2(a1, wx[1], xv);
            FMA2(a2, wx[2], xv);
            FMA2(a3, wx[3], xv);
        }
        float s0, s1, s2, s3, xl, xh;
        upk2(a0, xl, xh); s0 = xl + xh;
        upk2(a1, xl, xh); s1 = xl + xh;
        upk2(a2, xl, xh); s2 = xl + xh;
        upk2(a3, xl, xh); s3 = xl + xh;

        #pragma unroll
        for (int off = 16; off > 0; off >>= 1) {
            s0 += __shfl_xor_sync(full, s0, off);
            s1 += __shfl_xor_sync(full, s1, off);
            s2 += __shfl_xor_sync(full, s2, off);
            s3 += __shfl_xor_sync(full, s3, off);
        }

        // 5. activations + publish (lane 0): ONE atomic store = data + signal
        if (lane == 0) {
            const float i_ = sigf(s0 + bs0);
            const float f_ = sigf(s1 + bs1);
            const float g_ = tanhfast(s2 + bs2);
            const float o_ = sigf(s3 + bs3);
            c = fmaf(f_, c, i_ * g_);
            const float hnew = o_ * tanhfast(c);
            unsigned long long pub = pk_fu(hnew, (unsigned)(t + 1));
            asm volatile("st.relaxed.gpu.global.b64 [%0], %1;"
                         :: "l"(&g_hq[(t + 1) & 1][u]), "l"(pub));
        }
        // no trailing bar: next step's poll + single bar re-align everything
    }
}

// ---------------------------------------------------------------------------
// Kernel 2: out = h_S @ W_lin^T + b_lin   (O = 1)
// h_S lives in g_hq[S & 1] = g_hq[0] (tag field ignored)
// ---------------------------------------------------------------------------
__global__ void __launch_bounds__(1024) out_kernel(
    const float* __restrict__ Wlin,
    const float* __restrict__ blin,
    float* __restrict__ out)
{
    __shared__ float red[32];
    const int tid = threadIdx.x;
    float h = __uint_as_float((unsigned)(g_hq[0][tid] & 0xffffffffull));
    float v = h * Wlin[tid];
    #pragma unroll
    for (int off = 16; off > 0; off >>= 1)
        v += __shfl_xor_sync(0xffffffffu, v, off);
    if ((tid & 31) == 0) red[tid >> 5] = v;
    __syncthreads();
    if (tid < 32) {
        float xv = red[tid];
        #pragma unroll
        for (int off = 16; off > 0; off >>= 1)
            xv += __shfl_xor_sync(0xffffffffu, xv, off);
        if (tid == 0) out[0] = xv + blin[0];
    }
}

// ---------------------------------------------------------------------------
// kernel_launch (graph-capturable: plain launches only)
// Input order: input_seq, W_ih, W_hh, b_ih, b_hh, W_lin, b_lin (all fp32)
// ---------------------------------------------------------------------------
extern "C" void kernel_launch(void* const* d_in, const int* in_sizes, int n_in,
                              void* d_out, int out_size)
{
    const float* x    = (const float*)d_in[0];
    const float* Wih  = (const float*)d_in[1];
    const float* Whh  = (const float*)d_in[2];
    const float* bih  = (const float*)d_in[3];
    const float* bhh  = (const float*)d_in[4];
    const float* Wlin = (const float*)d_in[5];
    const float* blin = (const float*)d_in[6];
    float* out = (float*)d_out;

    reset_kernel<<<1, 1024>>>();
    rec_kernel<<<NCTA, 256>>>(x, Wih, Whh, bih, bhh);
    out_kernel<<<1, 1024>>>(Wlin, blin, out);
}

// round 12
// speedup vs baseline: 1.3466x; 1.3466x over previous
#include <cuda_runtime.h>
#include <cstdint>

// Problem sizes
#define S    4096
#define II   64
#define H    1024
#define NCTA 128
#define UPC  8        // hidden units per CTA (1 per warp, 8 warps)

// ---------------------------------------------------------------------------
// Device-global scratch (allocation-free rule: __device__ arrays only)
//
// g_h:  double-buffered hidden state (plain f32; h_t lives in slot t&1).
// g_cnt: monotonic CTA-step counter, the ONLY globally-polled word.
//        Discovery law (R3/R7/R11 regressions): chip-wide polling must be
//        O(100) pollers on ONE line. Here: 8 pollers/CTA = 1024 loads/RT on
//        a single broadcastable line (~3 req/cy) + 128 REDs/step.
// ---------------------------------------------------------------------------
__device__ float    g_h[2][H];
__device__ unsigned g_cnt;

// ---------------------------------------------------------------------------
// Helpers
// ---------------------------------------------------------------------------
__device__ __forceinline__ unsigned long long pk2(float x, float y) {
    unsigned long long r;
    asm("mov.b64 %0, {%1,%2};" : "=l"(r) : "f"(x), "f"(y));
    return r;
}
__device__ __forceinline__ void upk2(unsigned long long a, float& x, float& y) {
    asm("mov.b64 {%0,%1}, %2;" : "=f"(x), "=f"(y) : "l"(a));
}
#define FMA2(acc, a, b) \
    asm("fma.rn.f32x2 %0, %1, %2, %0;" : "+l"(acc) : "l"(a), "l"(b))

__device__ __forceinline__ float sigf(float x) {
    return 1.0f / (1.0f + __expf(-x));
}
__device__ __forceinline__ float tanhfast(float x) {
    float ax = fabsf(x);
    float e  = __expf(-2.0f * ax);          // in (0,1], overflow-free
    float t  = __fdividef(1.0f - e, 1.0f + e);
    return copysignf(t, x);
}

// ---------------------------------------------------------------------------
// Kernel 0: reset state between graph replays (determinism requirement)
// ---------------------------------------------------------------------------
__global__ void reset_kernel() {
    int i = threadIdx.x;
    if (i < H) { g_h[0][i] = 0.0f; g_h[1][i] = 0.0f; }
    if (i == 0) g_cnt = 0u;
}

// ---------------------------------------------------------------------------
// Kernel 1: persistent fused LSTM recurrence (input GEMM folded in).
// 128 CTAs x 256 threads, 1 CTA/SM. Warp w of CTA b owns hidden unit
// u = b*8 + w (gate rows u, H+u, 2H+u, 3H+u). Lane l holds W_hh column
// pairs (2l+64k) k=0..15 (64 packed f32x2) + W_ih column pair 2l in regs.
//
// Per-step protocol (TWO __syncthreads, gate fanout via SMEM flag):
//   1. prefetch x_{t+1} (tid<16, 256 B, triple-buffered SMEM)
//   2. GATE: lane 0 of EVERY warp polls ld.acquire.gpu(g_cnt) >= 128*t
//      (8 staggered pollers -> discovery ~ poll_period/8); first success
//      does st.release.cta(gflag = t). Everyone else spins on a ~30cy
//      acquire LDS loop until gflag >= t. Visibility chain:
//      producer red.release.gpu -> poller acquire.gpu -> flag release.cta
//      -> spinner acquire.cta  => all h stores visible to every thread.
//      (replaces tid0-poll + full __syncthreads wakeup: ~250-400cy saved)
//   3. SWEEP: one WEAK __ldcg float4 per thread -> hs[t&1]; bar B
//   4. matvec (LDS.64 + FMA2, W_hh + W_ih) -> shfl reduce -> activations
//   5. lane 0: weak __stcg publish of h_{t+1}[u]
//   6. trailing bar; tid 0: red.release.gpu.add(g_cnt, 1)
//      (release after the CTA barrier is cumulative over ALL warps' stores)
//
// Gate exactness: CTA's red for step t postdates all 8 warps' publishes.
// WAR safety: slot (t+1)&1 rewritten only in step t+1, gated on
// cnt >= 128(t+1), which needs every CTA's step-t red, ordered after that
// CTA's sweep reads of slot t&1 — exactly what step-(t+1) writers clobber.
// hs WAR: hs[(t+1)&1] is last read in step t-1, whose trailing bar +
// step-t bar B separate it from the step-(t+1) STS rewrite.
// ---------------------------------------------------------------------------
__global__ void __launch_bounds__(256, 1) rec_kernel(
    const float* __restrict__ x,
    const float* __restrict__ Wih,
    const float* __restrict__ Whh,
    const float* __restrict__ bih,
    const float* __restrict__ bhh)
{
    __shared__ __align__(16) float hs[2][H];     // staged h_t
    __shared__ __align__(16) float xs[3][II];    // staged x_t (triple buffer)
    __shared__ unsigned gflag;                   // monotonic step flag (fanout)

    const int tid  = threadIdx.x;
    const int lane = tid & 31;
    const int wrp  = tid >> 5;               // 0..7
    const int u    = blockIdx.x * UPC + wrp; // hidden unit 0..1023

    const unsigned fa = (unsigned)__cvta_generic_to_shared(&gflag);

    // ---- W_hh slice into registers (coalesced float2 loads) ----
    unsigned long long wq[4][16];
    #pragma unroll
    for (int g = 0; g < 4; g++) {
        const float2* base = (const float2*)(Whh + (size_t)(g * H + u) * H) + lane;
        #pragma unroll
        for (int k = 0; k < 16; k++) {
            float2 v = base[k * 32];
            wq[g][k] = pk2(v.x, v.y);
        }
    }
    // ---- W_ih slice (cols 2l, 2l+1 of rows u, H+u, 2H+u, 3H+u) ----
    unsigned long long wx[4];
    #pragma unroll
    for (int g = 0; g < 4; g++) {
        float2 v = ((const float2*)(Wih + (size_t)(g * H + u) * II))[lane];
        wx[g] = pk2(v.x, v.y);
    }
    // ---- biases (only lane 0 consumes them) ----
    float bs0 = bih[u]         + bhh[u];
    float bs1 = bih[H + u]     + bhh[H + u];
    float bs2 = bih[2 * H + u] + bhh[2 * H + u];
    float bs3 = bih[3 * H + u] + bhh[3 * H + u];

    // ---- preload x_0, init flag ----
    if (tid < 16) ((float4*)xs[0])[tid] = ((const float4*)x)[tid];
    if (tid == 0) gflag = 0u;
    __syncthreads();

    float c = 0.0f;                          // cell state (lane 0 only)
    const unsigned full = 0xffffffffu;

    #pragma unroll 1
    for (int t = 0; t < S; t++) {
        const int cur = t & 1;

        // 1. prefetch next step's input row (DRAM, hidden behind this step)
        if (t + 1 < S && tid < 16)
            ((float4*)xs[(t + 1) % 3])[tid] =
                __ldcg((const float4*)(x + (size_t)(t + 1) * II) + tid);

        // 2. GATE with SMEM-flag fanout
        if (t > 0) {
            if (lane == 0) {
                // 8 staggered pollers (one per warp) on the single counter
                const unsigned need = (unsigned)t * NCTA;
                for (;;) {
                    unsigned f;
                    asm volatile("ld.acquire.cta.shared.u32 %0, [%1];"
                                 : "=r"(f) : "r"(fa));
                    if (f >= (unsigned)t) break;
                    unsigned v;
                    asm volatile("ld.acquire.gpu.global.u32 %0, [%1];"
                                 : "=r"(v) : "l"(&g_cnt));
                    if (v >= need) {
                        asm volatile("st.release.cta.shared.u32 [%0], %1;"
                                     :: "r"(fa), "r"((unsigned)t));
                        break;
                    }
                }
            } else {
                // cheap SMEM spin (~30cy period, broadcast reads)
                unsigned f;
                do {
                    asm volatile("ld.acquire.cta.shared.u32 %0, [%1];"
                                 : "=r"(f) : "r"(fa));
                } while (f < (unsigned)t);
            }
        }

        // 3. SWEEP: single weak 16B load per thread (data stable post-gate)
        ((float4*)hs[cur])[tid] = __ldcg(((const float4*)g_h[cur]) + tid);
        __syncthreads();                     // bar B (stage-writes vs reads)

        // 4. mat-vec: W_hh * h_t  +  W_ih * x_t  (all packed f32x2)
        unsigned long long a0 = 0ull, a1 = 0ull, a2 = 0ull, a3 = 0ull;
        const unsigned long long* h2p = (const unsigned long long*)hs[cur] + lane;
        #pragma unroll
        for (int k = 0; k < 16; k++) {
            unsigned long long hv = h2p[k * 32];
            FMA2(a0, wq[0][k], hv);
            FMA2(a1, wq[1][k], hv);
            FMA2(a2, wq[2][k], hv);
            FMA2(a3, wq[3][k], hv);
        }
        {
            unsigned long long xv = ((const unsigned long long*)xs[t % 3])[lane];
            FMA2(a0, wx[0], xv);
            FMA2(a1, wx[1], xv);
            FMA2(a2, wx[2], xv);
            FMA2(a3, wx[3], xv);
        }
        float s0, s1, s2, s3, xl, xh;
        upk2(a0, xl, xh); s0 = xl + xh;
        upk2(a1, xl, xh); s1 = xl + xh;
        upk2(a2, xl, xh); s2 = xl + xh;
        upk2(a3, xl, xh); s3 = xl + xh;

        #pragma unroll
        for (int off = 16; off > 0; off >>= 1) {
            s0 += __shfl_xor_sync(full, s0, off);
            s1 += __shfl_xor_sync(full, s1, off);
            s2 += __shfl_xor_sync(full, s2, off);
            s3 += __shfl_xor_sync(full, s3, off);
        }

        // 5. activations + publish (lane 0)
        if (lane == 0) {
            const float i_ = sigf(s0 + bs0);
            const float f_ = sigf(s1 + bs1);
            const float g_ = tanhfast(s2 + bs2);
            const float o_ = sigf(s3 + bs3);
            c = fmaf(f_, c, i_ * g_);
            const float hnew = o_ * tanhfast(c);
            __stcg(&g_h[(t + 1) & 1][u], hnew);
        }

        // 6. trailing bar + single CTA-completion signal
        __syncthreads();
        if (tid == 0)
            asm volatile("red.release.gpu.global.add.u32 [%0], %1;"
                         :: "l"(&g_cnt), "r"(1u));
    }
}

// ---------------------------------------------------------------------------
// Kernel 2: out = h_S @ W_lin^T + b_lin   (O = 1)
// h_S lives in g_h[S & 1] = g_h[0]
// ---------------------------------------------------------------------------
__global__ void __launch_bounds__(1024) out_kernel(
    const float* __restrict__ Wlin,
    const float* __restrict__ blin,
    float* __restrict__ out)
{
    __shared__ float red[32];
    const int tid = threadIdx.x;
    float v = g_h[0][tid] * Wlin[tid];
    #pragma unroll
    for (int off = 16; off > 0; off >>= 1)
        v += __shfl_xor_sync(0xffffffffu, v, off);
    if ((tid & 31) == 0) red[tid >> 5] = v;
    __syncthreads();
    if (tid < 32) {
        float xv = red[tid];
        #pragma unroll
        for (int off = 16; off > 0; off >>= 1)
            xv += __shfl_xor_sync(0xffffffffu, xv, off);
        if (tid == 0) out[0] = xv + blin[0];
    }
}

// ---------------------------------------------------------------------------
// kernel_launch (graph-capturable: plain launches only)
// Input order: input_seq, W_ih, W_hh, b_ih, b_hh, W_lin, b_lin (all fp32)
// ---------------------------------------------------------------------------
extern "C" void kernel_launch(void* const* d_in, const int* in_sizes, int n_in,
                              void* d_out, int out_size)
{
    const float* x    = (const float*)d_in[0];
    const float* Wih  = (const float*)d_in[1];
    const float* Whh  = (const float*)d_in[2];
    const float* bih  = (const float*)d_in[3];
    const float* bhh  = (const float*)d_in[4];
    const float* Wlin = (const float*)d_in[5];
    const float* blin = (const float*)d_in[6];
    float* out = (float*)d_out;

    reset_kernel<<<1, 1024>>>();
    rec_kernel<<<NCTA, 256>>>(x, Wih, Whh, bih, bhh);
    out_kernel<<<1, 1024>>>(Wlin, blin, out);
}